// round 9
// baseline (speedup 1.0000x reference)
#include <cuda_runtime.h>
#include <cstdint>

// Problem constants
#define B 4
#define H 128
#define W 128
#define BINS 64
#define CBINS 32         // bins per pass (2 passes over same smem buffer)
#define KK 26            // 25 neighbors + current
#define KS 5

// Tiling: 8 x 16 output pixels per CTA, halo 2 -> 12 x 20 staged pixels
#define TH 8
#define TW 16
#define PH (TH + 4)      // 12
#define PW (TW + 4)      // 20
#define NPIX (PH * PW)   // 240 staged pixels
#define AS 132           // attn k-stride in floats (k*AS 16B-aligned)
#define THREADS 256

#define SREF_FLOATS (NPIX * CBINS)     // 7680  -> 30720 B ([pix][bin32])
#define SATTN_FLOATS (KK * AS)         // 3432  -> 13728 B
#define SMEM_BYTES ((SREF_FLOATS + SATTN_FLOATS) * 4)   // 44448 B -> 4 CTAs/SM

__device__ __forceinline__ void cp_async16(uint32_t dst, const void* src, int src_bytes) {
    asm volatile("cp.async.cg.shared.global [%0], [%1], 16, %2;\n"
                 :: "r"(dst), "l"(src), "r"(src_bytes) : "memory");
}

__global__ __launch_bounds__(THREADS, 4)
void agg_kernel(const float* __restrict__ attn,
                const float* __restrict__ refv,
                const float* __restrict__ curv,
                float* __restrict__ out) {
    extern __shared__ float smem[];
    float* s_ref  = smem;                 // [pix][32 bins], pix = lr*PW + lc
    float* s_attn = smem + SREF_FLOATS;   // [k][pix], pix = r*TW + c

    const int tid  = threadIdx.x;
    const int bidx = blockIdx.x;          // 512 blocks: 8 tw x 16 th x 4 batch
    const int tw = bidx & 7;
    const int th = (bidx >> 3) & 15;
    const int b  = bidx >> 7;
    const int h0 = th * TH;
    const int w0 = tw * TW;

    const float* refb = refv + (size_t)b * H * W * BINS;
    const uint32_t s_ref_b = (uint32_t)__cvta_generic_to_shared(s_ref);

    // Thread mapping for compute: 1 row x 4 px x 4 bins per pass
    const int bg = tid & 7;              // bin float4-group within pass (0..7)
    const int c0 = ((tid >> 3) & 3) * 4; // first output col: 0,4,8,12
    const int r  = tid >> 5;             // output row 0..7 (== warp id)

    const float* curb = curv + (size_t)b * H * W * BINS;
    float*       outb = out  + (size_t)b * H * W * BINS;

    // ---------- Stage pass-0 ref (bins 0..31) via cp.async ----------
    #pragma unroll
    for (int i = 0; i < 8; ++i) {        // 1920 chunks, 7.5/thread avg
        int idx = tid + i * THREADS;
        if (idx < NPIX * 8) {
            int g   = idx & 7;
            int pix = idx >> 3;
            int lr  = pix / PW;
            int lc  = pix - lr * PW;
            int gh  = h0 + lr - 2;
            int gw  = w0 + lc - 2;
            bool ok = ((unsigned)gh < (unsigned)H) && ((unsigned)gw < (unsigned)W);
            const float* src = refb + (((ok ? gh : 0) * W + (ok ? gw : 0)) * BINS + g * 4);
            uint32_t dst = s_ref_b + (uint32_t)((pix * CBINS + g * 4) * 4);
            cp_async16(dst, src, ok ? 16 : 0);
        }
    }
    asm volatile("cp.async.commit_group;\n" ::: "memory");

    // ---------- Stage attn (once), transposed [k][pix], division-free ----------
    {
        int pix = tid / KK;
        int k   = tid - pix * KK;
        #pragma unroll
        for (int i = 0; i < 13; ++i) {   // 3328 = 13*256 exactly
            int rr = pix >> 4, cc = pix & 15;
            float a = attn[(((b * H + h0 + rr) * W) + (w0 + cc)) * KK + k];
            s_attn[k * AS + pix] = a;
            k += 22; pix += 9;
            if (k >= KK) { k -= KK; pix += 1; }
        }
    }

    asm volatile("cp.async.wait_group 0;\n" ::: "memory");
    __syncthreads();

    // ================= Two passes over bin halves =================
    #pragma unroll 1
    for (int pass = 0; pass < 2; ++pass) {
        float4 acc[4];
        #pragma unroll
        for (int p = 0; p < 4; ++p) acc[p] = make_float4(0.f, 0.f, 0.f, 0.f);

        const float* arow = s_attn + r * TW + c0;

        #pragma unroll
        for (int di = 0; di < 5; ++di) {
            const float* vrow = s_ref + ((r + di) * PW + c0) * CBINS + bg * 4;
            float4 v[8];
            #pragma unroll
            for (int j = 0; j < 8; ++j)
                v[j] = *reinterpret_cast<const float4*>(vrow + j * CBINS);

            #pragma unroll
            for (int dj = 0; dj < 5; ++dj) {
                float4 a = *reinterpret_cast<const float4*>(arow + (di * KS + dj) * AS);
                acc[0].x = fmaf(a.x, v[0 + dj].x, acc[0].x);
                acc[0].y = fmaf(a.x, v[0 + dj].y, acc[0].y);
                acc[0].z = fmaf(a.x, v[0 + dj].z, acc[0].z);
                acc[0].w = fmaf(a.x, v[0 + dj].w, acc[0].w);
                acc[1].x = fmaf(a.y, v[1 + dj].x, acc[1].x);
                acc[1].y = fmaf(a.y, v[1 + dj].y, acc[1].y);
                acc[1].z = fmaf(a.y, v[1 + dj].z, acc[1].z);
                acc[1].w = fmaf(a.y, v[1 + dj].w, acc[1].w);
                acc[2].x = fmaf(a.z, v[2 + dj].x, acc[2].x);
                acc[2].y = fmaf(a.z, v[2 + dj].y, acc[2].y);
                acc[2].z = fmaf(a.z, v[2 + dj].z, acc[2].z);
                acc[2].w = fmaf(a.z, v[2 + dj].w, acc[2].w);
                acc[3].x = fmaf(a.w, v[3 + dj].x, acc[3].x);
                acc[3].y = fmaf(a.w, v[3 + dj].y, acc[3].y);
                acc[3].z = fmaf(a.w, v[3 + dj].z, acc[3].z);
                acc[3].w = fmaf(a.w, v[3 + dj].w, acc[3].w);
            }
        }

        // Epilogue for this pass: += attn[25]*current, coalesced float4
        {
            const int bo = pass * CBINS + bg * 4;
            float4 a25 = *reinterpret_cast<const float4*>(arow + 25 * AS);
            const float* ap = &a25.x;
            #pragma unroll
            for (int p = 0; p < 4; ++p) {
                int gaddr = ((h0 + r) * W + (w0 + c0 + p)) * BINS + bo;
                float4 cv = *reinterpret_cast<const float4*>(curb + gaddr);
                float av = ap[p];
                float4 o;
                o.x = fmaf(av, cv.x, acc[p].x);
                o.y = fmaf(av, cv.y, acc[p].y);
                o.z = fmaf(av, cv.z, acc[p].z);
                o.w = fmaf(av, cv.w, acc[p].w);
                *reinterpret_cast<float4*>(outb + gaddr) = o;
            }
        }

        if (pass == 0) {
            // Re-stage s_ref with bins 32..63
            __syncthreads();             // all reads of pass-0 data done
            #pragma unroll
            for (int i = 0; i < 8; ++i) {
                int idx = tid + i * THREADS;
                if (idx < NPIX * 8) {
                    int g   = idx & 7;
                    int pix = idx >> 3;
                    int lr  = pix / PW;
                    int lc  = pix - lr * PW;
                    int gh  = h0 + lr - 2;
                    int gw  = w0 + lc - 2;
                    bool ok = ((unsigned)gh < (unsigned)H) && ((unsigned)gw < (unsigned)W);
                    const float* src = refb +
                        (((ok ? gh : 0) * W + (ok ? gw : 0)) * BINS + CBINS + g * 4);
                    uint32_t dst = s_ref_b + (uint32_t)((pix * CBINS + g * 4) * 4);
                    cp_async16(dst, src, ok ? 16 : 0);
                }
            }
            asm volatile("cp.async.commit_group;\n" ::: "memory");
            asm volatile("cp.async.wait_group 0;\n" ::: "memory");
            __syncthreads();             // pass-1 data visible to all
        }
    }
}

extern "C" void kernel_launch(void* const* d_in, const int* in_sizes, int n_in,
                              void* d_out, int out_size) {
    const float* attn = (const float*)d_in[0];   // [4,128,128,26]
    const float* refv = (const float*)d_in[1];   // [4,128,128,64]
    const float* curv = (const float*)d_in[2];   // [4,128,128,64]
    float* out = (float*)d_out;                  // [4,128,128,64]

    cudaFuncSetAttribute(agg_kernel, cudaFuncAttributeMaxDynamicSharedMemorySize,
                         SMEM_BYTES);

    const int nblocks = B * (H / TH) * (W / TW);   // 4*16*8 = 512
    agg_kernel<<<nblocks, THREADS, SMEM_BYTES>>>(attn, refv, curv, out);
}

// round 10
// speedup vs baseline: 1.0019x; 1.0019x over previous
#include <cuda_runtime.h>
#include <cstdint>

// Problem constants
#define B 4
#define H 128
#define W 128
#define BINS 64
#define KK 26            // 25 neighbors + current
#define KS 5

// Tiling: 4 x 16 output pixels per CTA, halo 2 -> 8 x 20 staged pixels
#define TH 4
#define TW 16
#define PH (TH + 4)      // 8
#define PW (TW + 4)      // 20
#define NPIX (PH * PW)   // 160 staged pixels
#define AS 68            // attn k-stride in floats (>=64, 16B-aligned)
#define THREADS 256

#define SREF_FLOATS (NPIX * BINS)      // 10240 -> 40960 B (natural [pix][bin])
#define SATTN_FLOATS (KK * AS)         // 1768  -> 7072 B
#define SMEM_BYTES ((SREF_FLOATS + SATTN_FLOATS) * 4)   // 48032 B -> 4 CTAs/SM

__device__ __forceinline__ void cp_async16(uint32_t dst, const void* src, int src_bytes) {
    asm volatile("cp.async.cg.shared.global [%0], [%1], 16, %2;\n"
                 :: "r"(dst), "l"(src), "r"(src_bytes) : "memory");
}

__global__ __launch_bounds__(THREADS, 4)
void agg_kernel(const float* __restrict__ attn,
                const float* __restrict__ refv,
                const float* __restrict__ curv,
                float* __restrict__ out) {
    extern __shared__ float smem[];
    float* s_ref  = smem;                 // [pix][64 bins], pix = lr*PW + lc
    float* s_attn = smem + SREF_FLOATS;   // [k][pix], pix = r*TW + c

    const int tid  = threadIdx.x;
    const int bidx = blockIdx.x;          // 1024 blocks: 8 tw x 32 th x 4 batch
    const int tw = bidx & 7;
    const int th = (bidx >> 3) & 31;
    const int b  = bidx >> 8;
    const int h0 = th * TH;
    const int w0 = tw * TW;

    const float* refb = refv + (size_t)b * H * W * BINS;
    const uint32_t s_ref_b = (uint32_t)__cvta_generic_to_shared(s_ref);

    // ---------- Stage ref tile+halo via cp.async (natural layout) ----------
    // 160 pixels * 16 float4 chunks = 2560 = 10 per thread exactly.
    #pragma unroll
    for (int i = 0; i < (NPIX * 16) / THREADS; ++i) {
        int idx = tid + i * THREADS;
        int g   = idx & 15;
        int pix = idx >> 4;
        int lr  = pix / PW;
        int lc  = pix - lr * PW;
        int gh  = h0 + lr - 2;
        int gw  = w0 + lc - 2;
        bool ok = ((unsigned)gh < (unsigned)H) && ((unsigned)gw < (unsigned)W);
        const float* src = refb + (((ok ? gh : 0) * W + (ok ? gw : 0)) * BINS + g * 4);
        uint32_t dst = s_ref_b + (uint32_t)((pix * BINS + g * 4) * 4);
        cp_async16(dst, src, ok ? 16 : 0);   // zero-fill halo
    }
    asm volatile("cp.async.commit_group;\n" ::: "memory");

    // ---------- Stage attn tile, transposed [k][pix] ----------
    // 4*16*26 = 1664 elements; coalesced-ish reads, broadcast-friendly layout.
    #pragma unroll 1
    for (int idx = tid; idx < TH * TW * KK; idx += THREADS) {
        int pix = idx / KK;
        int k   = idx - pix * KK;
        int rr  = pix >> 4;
        int cc  = pix & 15;
        float a = attn[(((b * H + h0 + rr) * W) + (w0 + cc)) * KK + k];
        s_attn[k * AS + pix] = a;
    }

    asm volatile("cp.async.wait_group 0;\n" ::: "memory");
    __syncthreads();

    // ---------- Compute: thread = 1 row x 4 px x 4 bins ----------
    const int bg = tid & 15;             // bin float4-group 0..15
    const int c0 = ((tid >> 4) & 3) * 4; // first output col: 0,4,8,12
    const int r  = tid >> 6;             // output row 0..3

    float4 acc[4];
    #pragma unroll
    for (int p = 0; p < 4; ++p) acc[p] = make_float4(0.f, 0.f, 0.f, 0.f);

    const float* arow = s_attn + r * TW + c0;

    #pragma unroll
    for (int di = 0; di < 5; ++di) {
        // 8-wide window (4 outputs + 4 halo) of staged row (r+di)
        const float* vrow = s_ref + ((r + di) * PW + c0) * BINS + bg * 4;
        float4 v[8];
        #pragma unroll
        for (int j = 0; j < 8; ++j)
            v[j] = *reinterpret_cast<const float4*>(vrow + j * BINS);

        #pragma unroll
        for (int dj = 0; dj < 5; ++dj) {
            // one broadcast LDS.128: attn for this tap, 4 adjacent pixels
            float4 a = *reinterpret_cast<const float4*>(arow + (di * KS + dj) * AS);
            acc[0].x = fmaf(a.x, v[0 + dj].x, acc[0].x);
            acc[0].y = fmaf(a.x, v[0 + dj].y, acc[0].y);
            acc[0].z = fmaf(a.x, v[0 + dj].z, acc[0].z);
            acc[0].w = fmaf(a.x, v[0 + dj].w, acc[0].w);
            acc[1].x = fmaf(a.y, v[1 + dj].x, acc[1].x);
            acc[1].y = fmaf(a.y, v[1 + dj].y, acc[1].y);
            acc[1].z = fmaf(a.y, v[1 + dj].z, acc[1].z);
            acc[1].w = fmaf(a.y, v[1 + dj].w, acc[1].w);
            acc[2].x = fmaf(a.z, v[2 + dj].x, acc[2].x);
            acc[2].y = fmaf(a.z, v[2 + dj].y, acc[2].y);
            acc[2].z = fmaf(a.z, v[2 + dj].z, acc[2].z);
            acc[2].w = fmaf(a.z, v[2 + dj].w, acc[2].w);
            acc[3].x = fmaf(a.w, v[3 + dj].x, acc[3].x);
            acc[3].y = fmaf(a.w, v[3 + dj].y, acc[3].y);
            acc[3].z = fmaf(a.w, v[3 + dj].z, acc[3].z);
            acc[3].w = fmaf(a.w, v[3 + dj].w, acc[3].w);
        }
    }

    // ---------- Epilogue: += attn[25]*current, direct coalesced float4 ----------
    const float* curb = curv + (size_t)b * H * W * BINS;
    float*       outb = out  + (size_t)b * H * W * BINS;
    float4 a25 = *reinterpret_cast<const float4*>(arow + 25 * AS);
    const float* ap = &a25.x;
    #pragma unroll
    for (int p = 0; p < 4; ++p) {
        int gaddr = ((h0 + r) * W + (w0 + c0 + p)) * BINS + bg * 4;
        float4 cv = *reinterpret_cast<const float4*>(curb + gaddr);
        float av = ap[p];
        float4 o;
        o.x = fmaf(av, cv.x, acc[p].x);
        o.y = fmaf(av, cv.y, acc[p].y);
        o.z = fmaf(av, cv.z, acc[p].z);
        o.w = fmaf(av, cv.w, acc[p].w);
        *reinterpret_cast<float4*>(outb + gaddr) = o;
    }
}

extern "C" void kernel_launch(void* const* d_in, const int* in_sizes, int n_in,
                              void* d_out, int out_size) {
    const float* attn = (const float*)d_in[0];   // [4,128,128,26]
    const float* refv = (const float*)d_in[1];   // [4,128,128,64]
    const float* curv = (const float*)d_in[2];   // [4,128,128,64]
    float* out = (float*)d_out;                  // [4,128,128,64]

    cudaFuncSetAttribute(agg_kernel, cudaFuncAttributeMaxDynamicSharedMemorySize,
                         SMEM_BYTES);

    const int nblocks = B * (H / TH) * (W / TW);   // 4*32*8 = 1024
    agg_kernel<<<nblocks, THREADS, SMEM_BYTES>>>(attn, refv, curv, out);
}

// round 11
// speedup vs baseline: 1.1210x; 1.1189x over previous
#include <cuda_runtime.h>
#include <cstdint>

// Problem constants
#define B 4
#define H 128
#define W 128
#define BINS 64
#define KK 26            // 25 neighbors + current
#define KS 5

// Tiling: 8 x 16 output pixels per CTA, halo 2 -> 12 x 20 staged pixels
#define TH 8
#define TW 16
#define PH (TH + 4)      // 12
#define PW (TW + 4)      // 20
#define NPIX (PH * PW)   // 240 staged pixels
#define AS 132           // attn k-stride in floats (k*AS 16B-aligned)
#define THREADS 256

#define SREF_FLOATS (NPIX * BINS)      // 15360 -> 61440 B (natural [pix][bin])
#define SATTN_FLOATS (KK * AS)         // 3432  -> 13728 B
#define SMEM_BYTES ((SREF_FLOATS + SATTN_FLOATS) * 4)   // 75168 B -> 3 CTAs/SM

typedef unsigned long long ull;

__device__ __forceinline__ void cp_async16(uint32_t dst, const void* src, int src_bytes) {
    asm volatile("cp.async.cg.shared.global [%0], [%1], 16, %2;\n"
                 :: "r"(dst), "l"(src), "r"(src_bytes) : "memory");
}

// LDS.128 -> two packed u64 (each = 2 fp32 lanes), no repacking needed
__device__ __forceinline__ void lds_v2u64(ull& a, ull& b, uint32_t addr) {
    asm volatile("ld.shared.v2.u64 {%0, %1}, [%2];"
                 : "=l"(a), "=l"(b) : "r"(addr));
}

// packed fp32x2 FMA: d = a*b + d
__device__ __forceinline__ void fma2(ull& d, ull a, ull b) {
    asm volatile("fma.rn.f32x2 %0, %1, %2, %0;" : "+l"(d) : "l"(a), "l"(b));
}

__device__ __forceinline__ ull pack2(float a) {
    ull r;
    asm("mov.b64 %0, {%1, %1};" : "=l"(r) : "f"(a));
    return r;
}

__global__ __launch_bounds__(THREADS, 3)
void agg_kernel(const float* __restrict__ attn,
                const float* __restrict__ refv,
                const float* __restrict__ curv,
                float* __restrict__ out) {
    extern __shared__ float smem[];
    float* s_ref  = smem;                 // [pix][64 bins], pix = lr*PW + lc
    float* s_attn = smem + SREF_FLOATS;   // [k][pix], pix = r*TW + c

    const int tid  = threadIdx.x;
    const int bidx = blockIdx.x;          // 512 blocks: 8 tw x 16 th x 4 batch
    const int tw = bidx & 7;
    const int th = (bidx >> 3) & 15;
    const int b  = bidx >> 7;
    const int h0 = th * TH;
    const int w0 = tw * TW;

    const float* refb = refv + (size_t)b * H * W * BINS;
    const uint32_t s_ref_b = (uint32_t)__cvta_generic_to_shared(s_ref);

    // ---------- Stage ref tile+halo via cp.async (natural layout) ----------
    // 240 pixels * 16 float4 = 3840 chunks = 15 per thread exactly.
    #pragma unroll
    for (int i = 0; i < (NPIX * 16) / THREADS; ++i) {
        int idx = tid + i * THREADS;
        int g   = idx & 15;
        int pix = idx >> 4;
        int lr  = pix / PW;
        int lc  = pix - lr * PW;
        int gh  = h0 + lr - 2;
        int gw  = w0 + lc - 2;
        bool ok = ((unsigned)gh < (unsigned)H) && ((unsigned)gw < (unsigned)W);
        const float* src = refb + (((ok ? gh : 0) * W + (ok ? gw : 0)) * BINS + g * 4);
        uint32_t dst = s_ref_b + (uint32_t)((pix * BINS + g * 4) * 4);
        cp_async16(dst, src, ok ? 16 : 0);   // zero-fill halo
    }
    asm volatile("cp.async.commit_group;\n" ::: "memory");

    // ---------- Stage attn, transposed [k][pix], division-free walker ----------
    {
        int pix = tid / KK;
        int k   = tid - pix * KK;
        #pragma unroll
        for (int i = 0; i < 13; ++i) {   // 3328 = 13*256 exactly
            int rr = pix >> 4, cc = pix & 15;
            float a = attn[(((b * H + h0 + rr) * W) + (w0 + cc)) * KK + k];
            s_attn[k * AS + pix] = a;
            k += 22; pix += 9;
            if (k >= KK) { k -= KK; pix += 1; }
        }
    }

    asm volatile("cp.async.wait_group 0;\n" ::: "memory");
    __syncthreads();

    // ---------- Compute: thread = 2 rows x 4 px x 4 bins (f32x2 pairs) ----------
    const int bg = tid & 15;             // float4 bin group 0..15
    const int pg = tid >> 4;             // 0..15
    const int r0 = (pg >> 2) * 2;        // first output row: 0,2,4,6
    const int c0 = (pg & 3) * 4;         // first output col: 0,4,8,12

    ull acc0[4][2], acc1[4][2];
    #pragma unroll
    for (int p = 0; p < 4; ++p) {
        acc0[p][0] = 0ull; acc0[p][1] = 0ull;
        acc1[p][0] = 0ull; acc1[p][1] = 0ull;
    }

    const float* arow0 = s_attn + r0 * TW + c0;   // attn base, output row r0
    const float* arow1 = arow0 + TW;              // output row r0+1

    // Staged rows r0 .. r0+5: row (r0+arl) serves out-row r0 (di=arl, arl<=4)
    // and out-row r0+1 (di=arl-1, arl>=1) -> 2x vertical reuse of v window.
    #pragma unroll
    for (int arl = 0; arl < 6; ++arl) {
        const uint32_t vb = s_ref_b +
            (uint32_t)((((r0 + arl) * PW + c0) * BINS + bg * 4) * 4);

        // rolling 5-slot window: col j lives in slot j%5
        ull v[5][2];
        #pragma unroll
        for (int j = 0; j < 4; ++j)
            lds_v2u64(v[j][0], v[j][1], vb + j * (BINS * 4));

        #pragma unroll
        for (int dj = 0; dj < 5; ++dj) {
            if (dj < 4) {   // prefetch col dj+4 into slot (dj+4)%5 (old col dead)
                const int s = (dj + 4) % 5;
                lds_v2u64(v[s][0], v[s][1], vb + (dj + 4) * (BINS * 4));
            }
            if (arl <= 4) {   // compile-time pruned
                float4 a = *reinterpret_cast<const float4*>(arow0 + (arl * KS + dj) * AS);
                ull a0 = pack2(a.x), a1 = pack2(a.y), a2 = pack2(a.z), a3 = pack2(a.w);
                fma2(acc0[0][0], v[(0 + dj) % 5][0], a0);
                fma2(acc0[0][1], v[(0 + dj) % 5][1], a0);
                fma2(acc0[1][0], v[(1 + dj) % 5][0], a1);
                fma2(acc0[1][1], v[(1 + dj) % 5][1], a1);
                fma2(acc0[2][0], v[(2 + dj) % 5][0], a2);
                fma2(acc0[2][1], v[(2 + dj) % 5][1], a2);
                fma2(acc0[3][0], v[(3 + dj) % 5][0], a3);
                fma2(acc0[3][1], v[(3 + dj) % 5][1], a3);
            }
            if (arl >= 1) {   // compile-time pruned
                float4 a = *reinterpret_cast<const float4*>(arow1 + ((arl - 1) * KS + dj) * AS);
                ull a0 = pack2(a.x), a1 = pack2(a.y), a2 = pack2(a.z), a3 = pack2(a.w);
                fma2(acc1[0][0], v[(0 + dj) % 5][0], a0);
                fma2(acc1[0][1], v[(0 + dj) % 5][1], a0);
                fma2(acc1[1][0], v[(1 + dj) % 5][0], a1);
                fma2(acc1[1][1], v[(1 + dj) % 5][1], a1);
                fma2(acc1[2][0], v[(2 + dj) % 5][0], a2);
                fma2(acc1[2][1], v[(2 + dj) % 5][1], a2);
                fma2(acc1[3][0], v[(3 + dj) % 5][0], a3);
                fma2(acc1[3][1], v[(3 + dj) % 5][1], a3);
            }
        }
    }

    // ---------- Epilogue: += attn[25]*current, 128-bit packed path ----------
    const float* curb = curv + (size_t)b * H * W * BINS;
    float*       outb = out  + (size_t)b * H * W * BINS;
    #pragma unroll
    for (int rr = 0; rr < 2; ++rr) {
        float4 a25 = *reinterpret_cast<const float4*>(
            s_attn + 25 * AS + (r0 + rr) * TW + c0);
        ull ap[4] = { pack2(a25.x), pack2(a25.y), pack2(a25.z), pack2(a25.w) };
        ull (*accp)[2] = (rr == 0) ? acc0 : acc1;
        #pragma unroll
        for (int p = 0; p < 4; ++p) {
            int gaddr = ((h0 + r0 + rr) * W + (w0 + c0 + p)) * BINS + bg * 4;
            ulonglong2 cv = *reinterpret_cast<const ulonglong2*>(curb + gaddr);
            fma2(accp[p][0], cv.x, ap[p]);
            fma2(accp[p][1], cv.y, ap[p]);
            ulonglong2 o;
            o.x = accp[p][0];
            o.y = accp[p][1];
            *reinterpret_cast<ulonglong2*>(outb + gaddr) = o;
        }
    }
}

extern "C" void kernel_launch(void* const* d_in, const int* in_sizes, int n_in,
                              void* d_out, int out_size) {
    const float* attn = (const float*)d_in[0];   // [4,128,128,26]
    const float* refv = (const float*)d_in[1];   // [4,128,128,64]
    const float* curv = (const float*)d_in[2];   // [4,128,128,64]
    float* out = (float*)d_out;                  // [4,128,128,64]

    cudaFuncSetAttribute(agg_kernel, cudaFuncAttributeMaxDynamicSharedMemorySize,
                         SMEM_BYTES);

    const int nblocks = B * (H / TH) * (W / TW);   // 4*16*8 = 512
    agg_kernel<<<nblocks, THREADS, SMEM_BYTES>>>(attn, refv, curv, out);
}